// round 15
// baseline (speedup 1.0000x reference)
#include <cuda_runtime.h>

#define ITEMS 28
#define BLOCK 256
#define CHUNK (ITEMS * BLOCK)    // 7168 -> G=586 <= 592 co-resident @4 CTA/SM
#define NWARP (BLOCK / 32)       // 8
#define MAXBLKS 1024

__device__ float2 g_agg[MAXBLKS];    // per-block zero-state end state
__device__ int    g_flag[MAXBLKS];   // self-resetting handoff flags (init 0 at load)

__device__ __forceinline__ void get_params(const float* __restrict__ p,
                                           float& c1, float& c2,
                                           float& attack, float& decay, float& gain) {
    attack = fmaxf(p[0], 1e-7f);
    decay  = fmaxf(p[1], 1e-7f);
    c1 = fminf(fmaxf(p[2], 1e-7f), 0.99f);   // lowpass
    c2 = fminf(fmaxf(p[3], 1e-7f), 0.99f);   // highpass
    gain = fmaxf(p[4], 1e-7f);
}

__device__ __forceinline__ void mat_mul(float& c00, float& c10, float& c11,
                                        float a00, float a10, float a11,
                                        float b00, float b10, float b11) {
    c00 = a00 * b00;
    c10 = fmaf(a10, b00, a11 * b10);
    c11 = a11 * b11;
}

__device__ __forceinline__ void mat_sq(float& m00, float& m10, float& m11) {
    float n00 = m00 * m00;
    float n10 = m10 * (m00 + m11);
    float n11 = m11 * m11;
    m00 = n00; m10 = n10; m11 = n11;
}

// P = A^28 (binary 11100): 5 squarings + 3 muls
__device__ __forceinline__ void mat_pow28(float a00, float a10, float a11,
                                          float& M00, float& M10, float& M11) {
    M00 = 1.0f; M10 = 0.0f; M11 = 1.0f;
    float p00 = a00, p10 = a10, p11 = a11;
    #pragma unroll
    for (int b = 0; b < 5; b++) {
        if ((28 >> b) & 1) {
            float t00, t10, t11;
            mat_mul(t00, t10, t11, M00, M10, M11, p00, p10, p11);
            M00 = t00; M10 = t10; M11 = t11;
        }
        mat_sq(p00, p10, p11);
    }
}

// ---------------------------------------------------------------------------
// Single data kernel. Block b: sweep + scan, publish agg[b] (early), wait for
// agg[b-1] (neighbor-only; s_in = agg[b-1] is EXACT in fp32 since
// A^7168 ~ 5e-32 flushes), fold s_in into every thread's seed, replay + store
// the exact final output.
// ---------------------------------------------------------------------------
__global__ void __launch_bounds__(BLOCK, 4)
ng_main(const float* __restrict__ params, const float* __restrict__ x,
        float* __restrict__ out, int n) {
    float c1, c2, at, de, g;
    get_params(params, c1, c2, at, de, g);
    const float b1 = 1.0f - c1;
    const float dcoef = c2 * (c1 - 1.0f);
    const float bb = c2 * b1;

    const int tid = threadIdx.x;
    const int bid = blockIdx.x;
    const int lane = tid & 31, wid = tid >> 5;
    const long base = (long)bid * CHUNK + (long)tid * ITEMS;
    const bool full = (base + ITEMS) <= n;

    // ---- load once, keep in registers ----
    float xv[ITEMS];
    if (full) {
        const float4* xp = (const float4*)(x + base);
        #pragma unroll
        for (int k = 0; k < ITEMS / 4; k++) {
            float4 v = xp[k];
            xv[4*k+0] = v.x; xv[4*k+1] = v.y; xv[4*k+2] = v.z; xv[4*k+3] = v.w;
        }
    } else {
        #pragma unroll
        for (int j = 0; j < ITEMS; j++)
            xv[j] = (base + j < n) ? x[base + j] : 0.0f;
    }

    // ---- stride-4 zero-state sweep ----
    const float A2_00 = c1 * c1, A2_10 = dcoef * (c1 + c2), A2_11 = c2 * c2;
    const float A4_00 = A2_00 * A2_00, A4_10 = A2_10 * (A2_00 + A2_11), A4_11 = A2_11 * A2_11;
    const float q0x = b1,       q0y = bb;
    const float q1x = c1 * q0x, q1y = fmaf(dcoef, q0x, c2 * q0y);
    const float q2x = c1 * q1x, q2y = fmaf(dcoef, q1x, c2 * q1y);
    const float q3x = c1 * q2x, q3y = fmaf(dcoef, q2x, c2 * q2y);

    float v0 = 0.0f, v1 = 0.0f;
    #pragma unroll
    for (int k = 0; k < ITEMS / 4; k++) {
        float xa = xv[4*k+0], xb = xv[4*k+1], xc = xv[4*k+2], xd = xv[4*k+3];
        float u0 = fmaf(q2x, xb, q3x * xa) + fmaf(q0x, xd, q1x * xc);
        float u1 = fmaf(q2y, xb, q3y * xa) + fmaf(q0y, xd, q1y * xc);
        float v0n = fmaf(A4_00, v0, u0);
        v1 = fmaf(A4_10, v0, fmaf(A4_11, v1, u1));
        v0 = v0n;
    }

    // ---- P = A^28; vector-only KS scan; Ml = P^lane ----
    float pk00, pk10, pk11;
    mat_pow28(c1, dcoef, c2, pk00, pk10, pk11);
    float Ml00 = 1.0f, Ml10 = 0.0f, Ml11 = 1.0f;
    #pragma unroll
    for (int k = 0; k < 5; k++) {
        int dd = 1 << k;
        float o0 = __shfl_up_sync(0xffffffffu, v0, dd);
        float o1 = __shfl_up_sync(0xffffffffu, v1, dd);
        if (lane >= dd) {
            v0 = fmaf(pk00, o0, v0);
            v1 = fmaf(pk10, o0, fmaf(pk11, o1, v1));
        }
        if ((lane >> k) & 1) {
            float t00, t10, t11;
            mat_mul(t00, t10, t11, Ml00, Ml10, Ml11, pk00, pk10, pk11);
            Ml00 = t00; Ml10 = t10; Ml11 = t11;
        }
        mat_sq(pk00, pk10, pk11);   // ends: pk = P^32 (warp total)
    }

    float ve0 = __shfl_up_sync(0xffffffffu, v0, 1);
    float ve1 = __shfl_up_sync(0xffffffffu, v1, 1);
    if (lane == 0) { ve0 = 0.0f; ve1 = 0.0f; }

    __shared__ float2 wtotv[NWARP];
    __shared__ float2 prevv[NWARP];
    __shared__ float2 sh_sin;
    if (lane == 31) wtotv[wid] = make_float2(v0, v1);
    __syncthreads();
    if (tid == 0) {
        float s0 = 0.0f, s1 = 0.0f;
        #pragma unroll
        for (int w = 0; w < NWARP; w++) {
            prevv[w] = make_float2(s0, s1);
            float2 wv = wtotv[w];
            float ns0 = fmaf(pk00, s0, wv.x);
            s1 = fmaf(pk10, s0, fmaf(pk11, s1, wv.y));
            s0 = ns0;
        }
        // publish aggregate EARLY (release so agg is visible before flag)
        asm volatile("st.global.cg.v2.f32 [%0], {%1, %2};"
                     :: "l"(g_agg + bid), "f"(s0), "f"(s1) : "memory");
        asm volatile("st.release.gpu.global.b32 [%0], %1;"
                     :: "l"(g_flag + bid), "r"(1) : "memory");
        // wait for predecessor's aggregate (neighbor-only, early-published)
        if (bid > 0) {
            unsigned f;
            do {
                asm volatile("ld.acquire.gpu.global.b32 %0, [%1];"
                             : "=r"(f) : "l"(g_flag + bid - 1) : "memory");
            } while (f == 0u);
            float sx, sy;
            asm volatile("ld.global.cg.v2.f32 {%0, %1}, [%2];"
                         : "=f"(sx), "=f"(sy) : "l"(g_agg + bid - 1) : "memory");
            sh_sin = make_float2(sx, sy);
            // self-reset (unique consumer) -> deterministic across graph replays
            asm volatile("st.global.cg.b32 [%0], %1;"
                         :: "l"(g_flag + bid - 1), "r"(0) : "memory");
        } else {
            sh_sin = make_float2(0.0f, 0.0f);
        }
    }
    __syncthreads();

    // ---- exact thread seed: Ml*prevv[wid] + ve  +  (Ml*Mw)*s_in ----
    float2 pv = prevv[wid];
    float y1 = fmaf(Ml00, pv.x, ve0);
    float y2 = fmaf(Ml10, pv.x, fmaf(Ml11, pv.y, ve1));

    {
        // Mw = (P^32)^wid (3-bit chain on pk)
        float Mw00 = 1.0f, Mw10 = 0.0f, Mw11 = 1.0f;
        float w00 = pk00, w10 = pk10, w11 = pk11;
        #pragma unroll
        for (int k = 0; k < 3; k++) {
            if ((wid >> k) & 1) {
                float t00, t10, t11;
                mat_mul(t00, t10, t11, Mw00, Mw10, Mw11, w00, w10, w11);
                Mw00 = t00; Mw10 = t10; Mw11 = t11;
            }
            mat_sq(w00, w10, w11);
        }
        // Mf = Ml * Mw = A^(28*tid)  (underflows to 0 for large tid -> exact)
        float Mf00, Mf10, Mf11;
        mat_mul(Mf00, Mf10, Mf11, Ml00, Ml10, Ml11, Mw00, Mw10, Mw11);
        float2 si = sh_sin;
        y1 = fmaf(Mf00, si.x, y1);
        y2 = fmaf(Mf10, si.x, fmaf(Mf11, si.y, y2));
    }

    // ---- envelope (geometric) ----
    const float inv_n1 = 1.0f / (float)(n - 1);
    const float k1 = 1.0f / de;
    const float k2 = 1.0f / at + k1;
    const float t0 = (float)base * inv_n1;
    float e1 = g * __expf(-t0 * k1);
    float e2 = g * __expf(-t0 * k2);
    const float r1c = __expf(-inv_n1 * k1);
    const float r2c = __expf(-inv_n1 * k2);

    // ---- replay + store (final output) ----
    if (full) {
        float4* op = (float4*)(out + base);
        #pragma unroll
        for (int k = 0; k < ITEMS / 4; k++) {
            float4 o;
            #pragma unroll
            for (int s = 0; s < 4; s++) {
                float xn = xv[4*k + s];
                float t  = fmaf(dcoef, y1, bb * xn);
                y2 = fmaf(c2, y2, t);
                y1 = fmaf(c1, y1, b1 * xn);
                float val = y2 * (e1 - e2);
                e1 *= r1c; e2 *= r2c;
                if (s == 0) o.x = val; else if (s == 1) o.y = val;
                else if (s == 2) o.z = val; else o.w = val;
            }
            op[k] = o;
        }
    } else if (base < n) {
        #pragma unroll
        for (int j = 0; j < ITEMS; j++) {
            long idx = base + j;
            float xn = xv[j];
            float t  = fmaf(dcoef, y1, bb * xn);
            y2 = fmaf(c2, y2, t);
            y1 = fmaf(c1, y1, b1 * xn);
            float val = y2 * (e1 - e2);
            e1 *= r1c; e2 *= r2c;
            if (idx < n) out[idx] = val;
        }
    }
}

// ---------------------------------------------------------------------------
extern "C" void kernel_launch(void* const* d_in, const int* in_sizes, int n_in,
                              void* d_out, int out_size) {
    int i_par = 0, i_noise = 1;
    if (n_in >= 2 && in_sizes[0] > in_sizes[1]) { i_par = 1; i_noise = 0; }
    const float* params = (const float*)d_in[i_par];
    const float* noise  = (const float*)d_in[i_noise];
    float* out = (float*)d_out;
    const int n = in_sizes[i_noise];
    int G = (n + CHUNK - 1) / CHUNK;
    if (G > MAXBLKS) G = MAXBLKS;  // n = 2^22 -> G = 586 (co-resident, deadlock-free)

    ng_main<<<G, BLOCK>>>(params, noise, out, n);
}

// round 16
// speedup vs baseline: 1.7941x; 1.7941x over previous
#include <cuda_runtime.h>

#define ITEMS 32
#define BLOCK 256
#define WT    32                      // warmup threads
#define WARM  (WT * ITEMS)            // 1024 warmup samples: 0.99^1024 ~ 3.4e-5
#define OUTS  ((BLOCK - WT) * ITEMS)  // 7168 output samples per block
#define NWARP (BLOCK / 32)            // 8

__device__ __forceinline__ void get_params(const float* __restrict__ p,
                                           float& c1, float& c2,
                                           float& attack, float& decay, float& gain) {
    attack = fmaxf(p[0], 1e-7f);
    decay  = fmaxf(p[1], 1e-7f);
    c1 = fminf(fmaxf(p[2], 1e-7f), 0.99f);   // lowpass
    c2 = fminf(fmaxf(p[3], 1e-7f), 0.99f);   // highpass
    gain = fmaxf(p[4], 1e-7f);
}

__device__ __forceinline__ void mat_mul(float& c00, float& c10, float& c11,
                                        float a00, float a10, float a11,
                                        float b00, float b10, float b11) {
    c00 = a00 * b00;
    c10 = fmaf(a10, b00, a11 * b10);
    c11 = a11 * b11;
}

__device__ __forceinline__ void mat_sq(float& m00, float& m10, float& m11) {
    float n00 = m00 * m00;
    float n10 = m10 * (m00 + m11);
    float n11 = m11 * m11;
    m00 = n00; m10 = n10; m11 = n11;
}

// ---------------------------------------------------------------------------
// Single kernel, zero cross-CTA communication. Block b spans
// [b*OUTS - WARM, b*OUTS + OUTS): threads 0..WT-1 sweep the warmup (feeds the
// scan only); threads WT..255 sweep + replay + store the OUTS outputs.
// Truncation: state influence older than WARM samples <= 0.99^1024 ~ 3.4e-5,
// far below the 1e-3 threshold. Block 0's negative indices read as zeros,
// which IS the exact zero initial state.
// ---------------------------------------------------------------------------
__global__ void __launch_bounds__(BLOCK, 4)
ng_main(const float* __restrict__ params, const float* __restrict__ x,
        float* __restrict__ out, int n) {
    float c1, c2, at, de, g;
    get_params(params, c1, c2, at, de, g);
    const float b1 = 1.0f - c1;
    const float dcoef = c2 * (c1 - 1.0f);
    const float bb = c2 * b1;

    const int tid = threadIdx.x;
    const int bid = blockIdx.x;
    const int lane = tid & 31, wid = tid >> 5;
    const long base = (long)bid * OUTS - WARM + (long)tid * ITEMS;
    const bool full = (base >= 0) && (base + ITEMS <= n);

    // ---- load once, keep in registers ----
    float xv[ITEMS];
    if (full) {
        const float4* xp = (const float4*)(x + base);
        #pragma unroll
        for (int k = 0; k < ITEMS / 4; k++) {
            float4 v = xp[k];
            xv[4*k+0] = v.x; xv[4*k+1] = v.y; xv[4*k+2] = v.z; xv[4*k+3] = v.w;
        }
    } else {
        #pragma unroll
        for (int j = 0; j < ITEMS; j++) {
            long idx = base + j;
            xv[j] = (idx >= 0 && idx < n) ? x[idx] : 0.0f;
        }
    }

    // ---- stride-4 zero-state sweep ----
    const float A2_00 = c1 * c1, A2_10 = dcoef * (c1 + c2), A2_11 = c2 * c2;
    const float A4_00 = A2_00 * A2_00, A4_10 = A2_10 * (A2_00 + A2_11), A4_11 = A2_11 * A2_11;
    const float q0x = b1,       q0y = bb;
    const float q1x = c1 * q0x, q1y = fmaf(dcoef, q0x, c2 * q0y);
    const float q2x = c1 * q1x, q2y = fmaf(dcoef, q1x, c2 * q1y);
    const float q3x = c1 * q2x, q3y = fmaf(dcoef, q2x, c2 * q2y);

    float v0 = 0.0f, v1 = 0.0f;
    #pragma unroll
    for (int k = 0; k < ITEMS / 4; k++) {
        float xa = xv[4*k+0], xb = xv[4*k+1], xc = xv[4*k+2], xd = xv[4*k+3];
        float u0 = fmaf(q2x, xb, q3x * xa) + fmaf(q0x, xd, q1x * xc);
        float u1 = fmaf(q2y, xb, q3y * xa) + fmaf(q0y, xd, q1y * xc);
        float v0n = fmaf(A4_00, v0, u0);
        v1 = fmaf(A4_10, v0, fmaf(A4_11, v1, u1));
        v0 = v0n;
    }

    // ---- P = A^32 (5 squarings); vector-only KS scan; Ml = P^lane ----
    float pk00 = c1, pk10 = dcoef, pk11 = c2;
    #pragma unroll
    for (int k = 0; k < 5; k++) mat_sq(pk00, pk10, pk11);   // A^32

    float Ml00 = 1.0f, Ml10 = 0.0f, Ml11 = 1.0f;
    #pragma unroll
    for (int k = 0; k < 5; k++) {
        int dd = 1 << k;
        float o0 = __shfl_up_sync(0xffffffffu, v0, dd);
        float o1 = __shfl_up_sync(0xffffffffu, v1, dd);
        if (lane >= dd) {
            v0 = fmaf(pk00, o0, v0);
            v1 = fmaf(pk10, o0, fmaf(pk11, o1, v1));
        }
        if ((lane >> k) & 1) {
            float t00, t10, t11;
            mat_mul(t00, t10, t11, Ml00, Ml10, Ml11, pk00, pk10, pk11);
            Ml00 = t00; Ml10 = t10; Ml11 = t11;
        }
        mat_sq(pk00, pk10, pk11);   // ends: pk = (A^32)^32 (warp total)
    }

    float ve0 = __shfl_up_sync(0xffffffffu, v0, 1);
    float ve1 = __shfl_up_sync(0xffffffffu, v1, 1);
    if (lane == 0) { ve0 = 0.0f; ve1 = 0.0f; }

    __shared__ float2 wtotv[NWARP];
    __shared__ float2 prevv[NWARP];
    if (lane == 31) wtotv[wid] = make_float2(v0, v1);
    __syncthreads();
    if (tid == 0) {
        float s0 = 0.0f, s1 = 0.0f;
        #pragma unroll
        for (int w = 0; w < NWARP; w++) {
            prevv[w] = make_float2(s0, s1);
            float2 wv = wtotv[w];
            float ns0 = fmaf(pk00, s0, wv.x);
            s1 = fmaf(pk10, s0, fmaf(pk11, s1, wv.y));
            s0 = ns0;
        }
    }
    __syncthreads();

    // ---- output threads: seed, envelope, replay, store ----
    if (tid >= WT && base < n) {
        float2 pv = prevv[wid];
        float y1 = fmaf(Ml00, pv.x, ve0);
        float y2 = fmaf(Ml10, pv.x, fmaf(Ml11, pv.y, ve1));

        const float inv_n1 = 1.0f / (float)(n - 1);
        const float k1 = 1.0f / de;
        const float k2 = 1.0f / at + k1;
        const float t0 = (float)base * inv_n1;
        float e1 = g * __expf(-t0 * k1);
        float e2 = g * __expf(-t0 * k2);
        const float r1c = __expf(-inv_n1 * k1);
        const float r2c = __expf(-inv_n1 * k2);

        if (base + ITEMS <= n) {
            float4* op = (float4*)(out + base);
            #pragma unroll
            for (int k = 0; k < ITEMS / 4; k++) {
                float4 o;
                #pragma unroll
                for (int s = 0; s < 4; s++) {
                    float xn = xv[4*k + s];
                    float t  = fmaf(dcoef, y1, bb * xn);
                    y2 = fmaf(c2, y2, t);
                    y1 = fmaf(c1, y1, b1 * xn);
                    float val = y2 * (e1 - e2);
                    e1 *= r1c; e2 *= r2c;
                    if (s == 0) o.x = val; else if (s == 1) o.y = val;
                    else if (s == 2) o.z = val; else o.w = val;
                }
                op[k] = o;
            }
        } else {
            #pragma unroll
            for (int j = 0; j < ITEMS; j++) {
                long idx = base + j;
                float xn = xv[j];
                float t  = fmaf(dcoef, y1, bb * xn);
                y2 = fmaf(c2, y2, t);
                y1 = fmaf(c1, y1, b1 * xn);
                float val = y2 * (e1 - e2);
                e1 *= r1c; e2 *= r2c;
                if (idx < n) out[idx] = val;
            }
        }
    }
}

// ---------------------------------------------------------------------------
extern "C" void kernel_launch(void* const* d_in, const int* in_sizes, int n_in,
                              void* d_out, int out_size) {
    int i_par = 0, i_noise = 1;
    if (n_in >= 2 && in_sizes[0] > in_sizes[1]) { i_par = 1; i_noise = 0; }
    const float* params = (const float*)d_in[i_par];
    const float* noise  = (const float*)d_in[i_noise];
    float* out = (float*)d_out;
    const int n = in_sizes[i_noise];
    const int G = (n + OUTS - 1) / OUTS;   // n = 2^22 -> G = 586

    ng_main<<<G, BLOCK>>>(params, noise, out, n);
}